// round 5
// baseline (speedup 1.0000x reference)
#include <cuda_runtime.h>
#include <math.h>

// Problem constants (N,D,C,E,K = 100000,64,40,1600000,2)
#define NN 100000
#define DD 64
#define CC 40
#define EE 1600000
#define NB 98                    // build-kernel blocks (98*1024 = 100352 >= NN)

// ---- device scratch (__device__ globals; allocation APIs are banned) ----
__device__ int      g_mode;      // 64 if edge_index is int64, else 32
__device__ unsigned g_bar;       // grid barrier counter (zeroed each replay)
__device__ int      g_deg[NN];
__device__ float    g_dis[NN];
__device__ int      g_rowptr[NN + 1];
__device__ int      g_cursor[NN];
__device__ int      g_bsums[NB];
__device__ int2     g_colw[EE];  // packed (col, __float_as_int(dis[col]))
__device__ float2   g_buf0[(size_t)NN * (DD / 2)];   // hop-1 output

// ---------------------------------------------------------------------
// grid barrier for the all-resident build kernel
// ---------------------------------------------------------------------
__device__ __forceinline__ void gridbar(unsigned target) {
    __syncthreads();
    __threadfence();
    if (threadIdx.x == 0) {
        atomicAdd(&g_bar, 1u);
        while (*(volatile unsigned*)&g_bar < target) { }
        __threadfence();
    }
    __syncthreads();
}

// ---------------------------------------------------------------------
// 0) init: deg=1, zero barrier, detect edge dtype (int64 vals in [0,N))
// ---------------------------------------------------------------------
__global__ void k_init(const long long* __restrict__ ei, int n) {
    int i = blockIdx.x * blockDim.x + threadIdx.x;
    if (i < n) g_deg[i] = 1;
    if (blockIdx.x == 0 && threadIdx.x < 32) {
        if (threadIdx.x == 0) g_bar = 0u;
        int bad = 0;
        for (int k = threadIdx.x; k < 256; k += 32) {
            long long v = ei[k];
            if (v < 0 || v >= NN) bad = 1;
        }
        unsigned ball = __ballot_sync(0xFFFFFFFFu, bad);
        if (threadIdx.x == 0) g_mode = ball ? 32 : 64;
    }
}

// ---------------------------------------------------------------------
// 1) mega build: count degrees -> scan -> dis/cursor -> fill packed CSR
//    one kernel, 98 blocks x 1024 threads, manual grid barriers
// ---------------------------------------------------------------------
__global__ void __launch_bounds__(1024)
k_build(const void* __restrict__ ei, int n, int e) {
    const int tid      = blockIdx.x * 1024 + threadIdx.x;
    const int nthreads = NB * 1024;
    const int mode     = g_mode;
    const int epairs   = e / 2;          // E is even

    // ---- phase A: degree count (2 edges per iteration, vectorized) ----
    if (mode == 64) {
        const longlong2* p = (const longlong2*)ei;
        for (int i = tid; i < epairs; i += nthreads) {
            longlong2 v = p[i];
            atomicAdd(&g_deg[(int)v.x], 1);
            atomicAdd(&g_deg[(int)v.y], 1);
        }
    } else {
        const int2* p = (const int2*)ei;
        for (int i = tid; i < epairs; i += nthreads) {
            int2 v = p[i];
            atomicAdd(&g_deg[v.x], 1);
            atomicAdd(&g_deg[v.y], 1);
        }
    }
    gridbar(NB);

    // ---- phase B: exclusive scan of (deg-1) ----
    __shared__ int sh[1024];
    __shared__ int sh_off;
    int v = (tid < n) ? (g_deg[tid] - 1) : 0;
    sh[threadIdx.x] = v;
    __syncthreads();
    #pragma unroll
    for (int off = 1; off < 1024; off <<= 1) {
        int t = (threadIdx.x >= off) ? sh[threadIdx.x - off] : 0;
        __syncthreads();
        sh[threadIdx.x] += t;
        __syncthreads();
    }
    int incl = sh[threadIdx.x];
    if (threadIdx.x == 1023) g_bsums[blockIdx.x] = incl;   // block total
    gridbar(2 * NB);

    // sum of preceding block totals (warp 0 reduces, broadcast via shared)
    if (threadIdx.x < 32) {
        int s = 0;
        for (int i = threadIdx.x; i < blockIdx.x; i += 32) s += g_bsums[i];
        #pragma unroll
        for (int o = 16; o; o >>= 1) s += __shfl_xor_sync(0xFFFFFFFFu, s, o);
        if (threadIdx.x == 0) sh_off = s;
    }
    __syncthreads();
    int blk_off = sh_off;

    if (tid < n) {
        int p = (incl - v) + blk_off;
        g_rowptr[tid] = p;
        g_cursor[tid] = p;
        g_dis[tid]    = rsqrtf((float)g_deg[tid]);
        if (tid == n - 1) g_rowptr[n] = e;
    }
    gridbar(3 * NB);

    // ---- phase C: fill packed (col, dis[col]) ----
    if (mode == 64) {
        const longlong2* p = (const longlong2*)ei;
        for (int i = tid; i < epairs; i += nthreads) {
            longlong2 rv = p[i];
            longlong2 cv = p[epairs + i];
            int r0 = (int)rv.x, c0 = (int)cv.x;
            int r1 = (int)rv.y, c1 = (int)cv.y;
            int p0 = atomicAdd(&g_cursor[r0], 1);
            g_colw[p0] = make_int2(c0, __float_as_int(g_dis[c0]));
            int p1 = atomicAdd(&g_cursor[r1], 1);
            g_colw[p1] = make_int2(c1, __float_as_int(g_dis[c1]));
        }
    } else {
        const int2* p = (const int2*)ei;
        for (int i = tid; i < epairs; i += nthreads) {
            int2 rv = p[i];
            int2 cv = p[epairs + i];
            int p0 = atomicAdd(&g_cursor[rv.x], 1);
            g_colw[p0] = make_int2(cv.x, __float_as_int(g_dis[cv.x]));
            int p1 = atomicAdd(&g_cursor[rv.y], 1);
            g_colw[p1] = make_int2(cv.y, __float_as_int(g_dis[cv.y]));
        }
    }
}

// ---------------------------------------------------------------------
// 2) hop 1: warp per row, staged (col,w) + 4-edge unroll
//    g_buf0[r] = dis[r]*sum_c dis[c]*x[c] + dis[r]^2*x[r]
// ---------------------------------------------------------------------
__global__ void __launch_bounds__(256)
k_prop1(const float* __restrict__ x, int n) {
    int warp = (blockIdx.x * blockDim.x + threadIdx.x) >> 5;
    int lane = threadIdx.x & 31;
    if (warp >= n) return;
    int beg = g_rowptr[warp];
    int end = g_rowptr[warp + 1];
    float accx = 0.f, accy = 0.f;

    for (int base = beg; base < end; base += 32) {
        int m = end - base; if (m > 32) m = 32;
        int2 cw = make_int2(0, 0);
        if (lane < m) cw = g_colw[base + lane];
        int j = 0;
        for (; j + 4 <= m; j += 4) {
            int c0 = __shfl_sync(0xFFFFFFFFu, cw.x, j);
            int c1 = __shfl_sync(0xFFFFFFFFu, cw.x, j + 1);
            int c2 = __shfl_sync(0xFFFFFFFFu, cw.x, j + 2);
            int c3 = __shfl_sync(0xFFFFFFFFu, cw.x, j + 3);
            float w0 = __int_as_float(__shfl_sync(0xFFFFFFFFu, cw.y, j));
            float w1 = __int_as_float(__shfl_sync(0xFFFFFFFFu, cw.y, j + 1));
            float w2 = __int_as_float(__shfl_sync(0xFFFFFFFFu, cw.y, j + 2));
            float w3 = __int_as_float(__shfl_sync(0xFFFFFFFFu, cw.y, j + 3));
            float2 v0 = *(const float2*)(x + (size_t)c0 * DD + lane * 2);
            float2 v1 = *(const float2*)(x + (size_t)c1 * DD + lane * 2);
            float2 v2 = *(const float2*)(x + (size_t)c2 * DD + lane * 2);
            float2 v3 = *(const float2*)(x + (size_t)c3 * DD + lane * 2);
            accx += w0 * v0.x + w1 * v1.x + w2 * v2.x + w3 * v3.x;
            accy += w0 * v0.y + w1 * v1.y + w2 * v2.y + w3 * v3.y;
        }
        for (; j < m; j++) {
            int   c0 = __shfl_sync(0xFFFFFFFFu, cw.x, j);
            float w0 = __int_as_float(__shfl_sync(0xFFFFFFFFu, cw.y, j));
            float2 v0 = *(const float2*)(x + (size_t)c0 * DD + lane * 2);
            accx += w0 * v0.x;
            accy += w0 * v0.y;
        }
    }
    float dr = g_dis[warp];
    float sl = dr * dr;
    float2 xs = *(const float2*)(x + (size_t)warp * DD + lane * 2);
    float2 o;
    o.x = dr * accx + sl * xs.x;
    o.y = dr * accy + sl * xs.y;
    g_buf0[(size_t)warp * (DD / 2) + lane] = o;
}

// ---------------------------------------------------------------------
// 3) fused hop 2 + GEMM + log_softmax
// ---------------------------------------------------------------------
__global__ void __launch_bounds__(256)
k_prop2_gemm(const float* __restrict__ W, const float* __restrict__ b,
             float* __restrict__ out, int n) {
    __shared__ float Ws[DD * CC];
    __shared__ float bs[CC];
    for (int i = threadIdx.x; i < DD * CC; i += blockDim.x) Ws[i] = W[i];
    for (int i = threadIdx.x; i < CC; i += blockDim.x) bs[i] = b[i];
    __syncthreads();

    int warp = (blockIdx.x * blockDim.x + threadIdx.x) >> 5;
    int lane = threadIdx.x & 31;
    if (warp >= n) return;

    // ---- hop 2 (gather from g_buf0) ----
    int beg = g_rowptr[warp];
    int end = g_rowptr[warp + 1];
    float accx = 0.f, accy = 0.f;
    for (int base = beg; base < end; base += 32) {
        int m = end - base; if (m > 32) m = 32;
        int2 cw = make_int2(0, 0);
        if (lane < m) cw = g_colw[base + lane];
        int j = 0;
        for (; j + 4 <= m; j += 4) {
            int c0 = __shfl_sync(0xFFFFFFFFu, cw.x, j);
            int c1 = __shfl_sync(0xFFFFFFFFu, cw.x, j + 1);
            int c2 = __shfl_sync(0xFFFFFFFFu, cw.x, j + 2);
            int c3 = __shfl_sync(0xFFFFFFFFu, cw.x, j + 3);
            float w0 = __int_as_float(__shfl_sync(0xFFFFFFFFu, cw.y, j));
            float w1 = __int_as_float(__shfl_sync(0xFFFFFFFFu, cw.y, j + 1));
            float w2 = __int_as_float(__shfl_sync(0xFFFFFFFFu, cw.y, j + 2));
            float w3 = __int_as_float(__shfl_sync(0xFFFFFFFFu, cw.y, j + 3));
            float2 v0 = g_buf0[(size_t)c0 * (DD / 2) + lane];
            float2 v1 = g_buf0[(size_t)c1 * (DD / 2) + lane];
            float2 v2 = g_buf0[(size_t)c2 * (DD / 2) + lane];
            float2 v3 = g_buf0[(size_t)c3 * (DD / 2) + lane];
            accx += w0 * v0.x + w1 * v1.x + w2 * v2.x + w3 * v3.x;
            accy += w0 * v0.y + w1 * v1.y + w2 * v2.y + w3 * v3.y;
        }
        for (; j < m; j++) {
            int   c0 = __shfl_sync(0xFFFFFFFFu, cw.x, j);
            float w0 = __int_as_float(__shfl_sync(0xFFFFFFFFu, cw.y, j));
            float2 v0 = g_buf0[(size_t)c0 * (DD / 2) + lane];
            accx += w0 * v0.x;
            accy += w0 * v0.y;
        }
    }
    float dr = g_dis[warp];
    float sl = dr * dr;
    float2 xs = g_buf0[(size_t)warp * (DD / 2) + lane];
    float hx = dr * accx + sl * xs.x;   // feature 2*lane
    float hy = dr * accy + sl * xs.y;   // feature 2*lane+1

    // ---- GEMM: lane owns output cols {lane, lane+32(if<40)} ----
    float acc0 = bs[lane];
    float acc1 = (lane < CC - 32) ? bs[lane + 32] : 0.f;
    #pragma unroll
    for (int k = 0; k < DD; k++) {
        float xk = __shfl_sync(0xFFFFFFFFu, (k & 1) ? hy : hx, k >> 1);
        acc0 += xk * Ws[k * CC + lane];
        if (lane < CC - 32) acc1 += xk * Ws[k * CC + lane + 32];
    }

    // ---- log_softmax over 40 logits ----
    float m = acc0;
    if (lane < CC - 32) m = fmaxf(m, acc1);
    #pragma unroll
    for (int off = 16; off; off >>= 1)
        m = fmaxf(m, __shfl_xor_sync(0xFFFFFFFFu, m, off));

    float s = __expf(acc0 - m);
    if (lane < CC - 32) s += __expf(acc1 - m);
    #pragma unroll
    for (int off = 16; off; off >>= 1)
        s += __shfl_xor_sync(0xFFFFFFFFu, s, off);

    float lse = m + __logf(s);
    out[(size_t)warp * CC + lane] = acc0 - lse;
    if (lane < CC - 32) out[(size_t)warp * CC + lane + 32] = acc1 - lse;
}

// ---------------------------------------------------------------------
extern "C" void kernel_launch(void* const* d_in, const int* in_sizes, int n_in,
                              void* d_out, int out_size) {
    const float* x  = (const float*)d_in[0];
    const void*  ei = (const void*)d_in[1];
    const float* W  = (const float*)d_in[2];
    const float* b  = (const float*)d_in[3];
    float* out = (float*)d_out;

    const int n = NN, e = EE;
    const int T = 256;

    k_init <<<(n + T - 1) / T, T>>>((const long long*)ei, n);
    k_build<<<NB, 1024>>>(ei, n, e);

    int prop_blocks = (n * 32 + T - 1) / T;   // warp per row
    k_prop1      <<<prop_blocks, T>>>(x, n);
    k_prop2_gemm <<<prop_blocks, T>>>(W, b, out, n);
}

// round 6
// speedup vs baseline: 1.0120x; 1.0120x over previous
#include <cuda_runtime.h>
#include <math.h>

// Problem constants (N,D,C,E,K = 100000,64,40,1600000,2)
#define NN 100000
#define DD 64
#define CC 40
#define EE 1600000
#define NB 98                    // build-kernel blocks (98*1024 >= NN, all co-resident)
#define D4 (DD / 4)              // 16 float4 per row

// ---- device scratch (__device__ globals; allocation APIs are banned) ----
__device__ int      g_mode;      // 64 if edge_index is int64, else 32
__device__ unsigned g_bar;       // grid barrier counter
__device__ int      g_deg[NN];
__device__ float    g_dis[NN];
__device__ int      g_rowptr[NN + 1];
__device__ int      g_cursor[NN];
__device__ int      g_bsums[NB];
__device__ int2     g_colw[EE];  // packed (col, __float_as_int(dis[col]))
__device__ float4   g_buf0[(size_t)NN * D4];   // hop-1 output

// ---------------------------------------------------------------------
__device__ __forceinline__ void gridbar(unsigned target) {
    __syncthreads();
    __threadfence();
    if (threadIdx.x == 0) {
        atomicAdd(&g_bar, 1u);
        while (*(volatile unsigned*)&g_bar < target) { }
        __threadfence();
    }
    __syncthreads();
}

// ---------------------------------------------------------------------
// 1) mega build: init+detect -> count -> scan -> dis/cursor -> fill CSR
// ---------------------------------------------------------------------
__global__ void __launch_bounds__(1024)
k_build(const void* __restrict__ ei, int n, int e) {
    const int tid      = blockIdx.x * 1024 + threadIdx.x;
    const int nthreads = NB * 1024;
    const int epairs   = e / 2;          // E is even

    // ---- phase 0: deg=1 init + dtype detect ----
    for (int i = tid; i < n; i += nthreads) g_deg[i] = 1;
    if (blockIdx.x == 0 && threadIdx.x < 32) {
        const long long* e64 = (const long long*)ei;
        int bad = 0;
        for (int k = threadIdx.x; k < 256; k += 32) {
            long long v = e64[k];
            if (v < 0 || v >= NN) bad = 1;
        }
        unsigned ball = __ballot_sync(0xFFFFFFFFu, bad);
        if (threadIdx.x == 0) g_mode = ball ? 32 : 64;
    }
    gridbar(NB);
    const int mode = g_mode;

    // ---- phase A: degree count ----
    if (mode == 64) {
        const longlong2* p = (const longlong2*)ei;
        for (int i = tid; i < epairs; i += nthreads) {
            longlong2 v = p[i];
            atomicAdd(&g_deg[(int)v.x], 1);
            atomicAdd(&g_deg[(int)v.y], 1);
        }
    } else {
        const int2* p = (const int2*)ei;
        for (int i = tid; i < epairs; i += nthreads) {
            int2 v = p[i];
            atomicAdd(&g_deg[v.x], 1);
            atomicAdd(&g_deg[v.y], 1);
        }
    }
    gridbar(2 * NB);

    // ---- phase B: exclusive scan of (deg-1) ----
    __shared__ int sh[1024];
    __shared__ int sh_off;
    int v = (tid < n) ? (g_deg[tid] - 1) : 0;
    sh[threadIdx.x] = v;
    __syncthreads();
    #pragma unroll
    for (int off = 1; off < 1024; off <<= 1) {
        int t = (threadIdx.x >= off) ? sh[threadIdx.x - off] : 0;
        __syncthreads();
        sh[threadIdx.x] += t;
        __syncthreads();
    }
    int incl = sh[threadIdx.x];
    if (threadIdx.x == 1023) g_bsums[blockIdx.x] = incl;
    gridbar(3 * NB);

    if (threadIdx.x < 32) {
        int s = 0;
        for (int i = threadIdx.x; i < blockIdx.x; i += 32) s += g_bsums[i];
        #pragma unroll
        for (int o = 16; o; o >>= 1) s += __shfl_xor_sync(0xFFFFFFFFu, s, o);
        if (threadIdx.x == 0) sh_off = s;
    }
    __syncthreads();
    int blk_off = sh_off;

    if (tid < n) {
        int p = (incl - v) + blk_off;
        g_rowptr[tid] = p;
        g_cursor[tid] = p;
        g_dis[tid]    = rsqrtf((float)g_deg[tid]);
        if (tid == n - 1) g_rowptr[n] = e;
    }
    gridbar(4 * NB);

    // ---- phase C: fill packed (col, dis[col]) ----
    if (mode == 64) {
        const longlong2* p = (const longlong2*)ei;
        for (int i = tid; i < epairs; i += nthreads) {
            longlong2 rv = p[i];
            longlong2 cv = p[epairs + i];
            int c0 = (int)cv.x, c1 = (int)cv.y;
            int p0 = atomicAdd(&g_cursor[(int)rv.x], 1);
            g_colw[p0] = make_int2(c0, __float_as_int(g_dis[c0]));
            int p1 = atomicAdd(&g_cursor[(int)rv.y], 1);
            g_colw[p1] = make_int2(c1, __float_as_int(g_dis[c1]));
        }
    } else {
        const int2* p = (const int2*)ei;
        for (int i = tid; i < epairs; i += nthreads) {
            int2 rv = p[i];
            int2 cv = p[epairs + i];
            int p0 = atomicAdd(&g_cursor[rv.x], 1);
            g_colw[p0] = make_int2(cv.x, __float_as_int(g_dis[cv.x]));
            int p1 = atomicAdd(&g_cursor[rv.y], 1);
            g_colw[p1] = make_int2(cv.y, __float_as_int(g_dis[cv.y]));
        }
    }
}

// ---------------------------------------------------------------------
// half-warp gather core: warp handles one row; lanes 0-15 process even
// edges, lanes 16-31 odd edges; each lane owns 4 features (float4).
// Returns acc4 = sum_c w_c * src[c] for features 4*(lane&15)..+3
// (replicated across both halves after the xor-16 reduction).
// ---------------------------------------------------------------------
__device__ __forceinline__ float4
gather_row(const float4* __restrict__ src, int beg, int end, int lane) {
    const int hl   = lane >> 4;        // 0 = low half, 1 = high half
    const int fidx = lane & 15;        // float4 index within row
    float4 acc = make_float4(0.f, 0.f, 0.f, 0.f);

    for (int base = beg; base < end; base += 32) {
        int m = end - base; if (m > 32) m = 32;
        int2 cw = make_int2(0, 0);                    // w=0 pad: gathers row 0 harmlessly
        if (lane < m) cw = g_colw[base + lane];
        int me = (m + 1) & ~1;                        // round up to even
        int j = 0;
        for (; j + 8 <= me; j += 8) {
            int   s0 = j     + hl, s1 = j + 2 + hl, s2 = j + 4 + hl, s3 = j + 6 + hl;
            int   c0 = __shfl_sync(0xFFFFFFFFu, cw.x, s0);
            int   c1 = __shfl_sync(0xFFFFFFFFu, cw.x, s1);
            int   c2 = __shfl_sync(0xFFFFFFFFu, cw.x, s2);
            int   c3 = __shfl_sync(0xFFFFFFFFu, cw.x, s3);
            float w0 = __int_as_float(__shfl_sync(0xFFFFFFFFu, cw.y, s0));
            float w1 = __int_as_float(__shfl_sync(0xFFFFFFFFu, cw.y, s1));
            float w2 = __int_as_float(__shfl_sync(0xFFFFFFFFu, cw.y, s2));
            float w3 = __int_as_float(__shfl_sync(0xFFFFFFFFu, cw.y, s3));
            float4 v0 = src[(size_t)c0 * D4 + fidx];
            float4 v1 = src[(size_t)c1 * D4 + fidx];
            float4 v2 = src[(size_t)c2 * D4 + fidx];
            float4 v3 = src[(size_t)c3 * D4 + fidx];
            acc.x += w0 * v0.x + w1 * v1.x + w2 * v2.x + w3 * v3.x;
            acc.y += w0 * v0.y + w1 * v1.y + w2 * v2.y + w3 * v3.y;
            acc.z += w0 * v0.z + w1 * v1.z + w2 * v2.z + w3 * v3.z;
            acc.w += w0 * v0.w + w1 * v1.w + w2 * v2.w + w3 * v3.w;
        }
        for (; j < me; j += 2) {
            int   s0 = j + hl;
            int   c0 = __shfl_sync(0xFFFFFFFFu, cw.x, s0);
            float w0 = __int_as_float(__shfl_sync(0xFFFFFFFFu, cw.y, s0));
            float4 v0 = src[(size_t)c0 * D4 + fidx];
            acc.x += w0 * v0.x;
            acc.y += w0 * v0.y;
            acc.z += w0 * v0.z;
            acc.w += w0 * v0.w;
        }
    }
    // combine the two halves
    acc.x += __shfl_xor_sync(0xFFFFFFFFu, acc.x, 16);
    acc.y += __shfl_xor_sync(0xFFFFFFFFu, acc.y, 16);
    acc.z += __shfl_xor_sync(0xFFFFFFFFu, acc.z, 16);
    acc.w += __shfl_xor_sync(0xFFFFFFFFu, acc.w, 16);
    return acc;
}

// ---------------------------------------------------------------------
// 2) hop 1: g_buf0[r] = dis[r]*gather(x) + dis[r]^2*x[r]
// ---------------------------------------------------------------------
__global__ void __launch_bounds__(256)
k_prop1(const float4* __restrict__ x4, int n) {
    if (blockIdx.x == 0 && threadIdx.x == 0) g_bar = 0u;   // reset for next replay
    int warp = (blockIdx.x * blockDim.x + threadIdx.x) >> 5;
    int lane = threadIdx.x & 31;
    if (warp >= n) return;

    float4 acc = gather_row(x4, g_rowptr[warp], g_rowptr[warp + 1], lane);

    int fidx = lane & 15;
    float dr = g_dis[warp];
    float sl = dr * dr;
    float4 xs = x4[(size_t)warp * D4 + fidx];
    float4 o;
    o.x = dr * acc.x + sl * xs.x;
    o.y = dr * acc.y + sl * xs.y;
    o.z = dr * acc.z + sl * xs.z;
    o.w = dr * acc.w + sl * xs.w;
    if (lane < 16) g_buf0[(size_t)warp * D4 + fidx] = o;
}

// ---------------------------------------------------------------------
// 3) fused hop 2 + GEMM + log_softmax
//    smem: Wt[c][k] transposed, pad stride 68 floats (conflict-free LDS.128)
// ---------------------------------------------------------------------
#define WT_STRIDE 68
__global__ void __launch_bounds__(256)
k_prop2_gemm(const float* __restrict__ W, const float* __restrict__ b,
             float* __restrict__ out, int n) {
    __shared__ float Wt[CC * WT_STRIDE];        // 40*68*4 = 10.9KB
    __shared__ float bs[CC];
    __shared__ float4 hsm[8][D4];               // per-warp h staging (8 warps)

    for (int i = threadIdx.x; i < DD * CC; i += blockDim.x) {
        int k = i / CC, c = i % CC;
        Wt[c * WT_STRIDE + k] = W[i];
    }
    for (int i = threadIdx.x; i < CC; i += blockDim.x) bs[i] = b[i];
    __syncthreads();

    int warp  = (blockIdx.x * blockDim.x + threadIdx.x) >> 5;
    int wblk  = (threadIdx.x >> 5);
    int lane  = threadIdx.x & 31;
    if (warp >= n) return;

    // ---- hop 2 ----
    float4 acc = gather_row(g_buf0, g_rowptr[warp], g_rowptr[warp + 1], lane);

    int fidx = lane & 15;
    float dr = g_dis[warp];
    float sl = dr * dr;
    float4 xs = g_buf0[(size_t)warp * D4 + fidx];
    float4 h;
    h.x = dr * acc.x + sl * xs.x;
    h.y = dr * acc.y + sl * xs.y;
    h.z = dr * acc.z + sl * xs.z;
    h.w = dr * acc.w + sl * xs.w;
    if (lane < 16) hsm[wblk][fidx] = h;
    __syncwarp();

    // ---- GEMM: lane owns cols {lane, lane+32 (lanes 0..7)} ----
    float acc0 = bs[lane];
    float acc1 = (lane < CC - 32) ? bs[lane + 32] : 0.f;
    const float4* w0p = (const float4*)(Wt + lane * WT_STRIDE);
    const float4* w1p = (const float4*)(Wt + (lane + 32) * WT_STRIDE);
    bool has2 = (lane < CC - 32);
    #pragma unroll
    for (int k4 = 0; k4 < D4; k4++) {
        float4 hv = hsm[wblk][k4];              // broadcast LDS.128
        float4 w0 = w0p[k4];
        acc0 += hv.x * w0.x + hv.y * w0.y + hv.z * w0.z + hv.w * w0.w;
        if (has2) {
            float4 w1 = w1p[k4];
            acc1 += hv.x * w1.x + hv.y * w1.y + hv.z * w1.z + hv.w * w1.w;
        }
    }

    // ---- log_softmax over 40 logits ----
    float m = acc0;
    if (has2) m = fmaxf(m, acc1);
    #pragma unroll
    for (int off = 16; off; off >>= 1)
        m = fmaxf(m, __shfl_xor_sync(0xFFFFFFFFu, m, off));

    float s = __expf(acc0 - m);
    if (has2) s += __expf(acc1 - m);
    #pragma unroll
    for (int off = 16; off; off >>= 1)
        s += __shfl_xor_sync(0xFFFFFFFFu, s, off);

    float lse = m + __logf(s);
    out[(size_t)warp * CC + lane] = acc0 - lse;
    if (has2) out[(size_t)warp * CC + lane + 32] = acc1 - lse;
}

// ---------------------------------------------------------------------
extern "C" void kernel_launch(void* const* d_in, const int* in_sizes, int n_in,
                              void* d_out, int out_size) {
    const float* x  = (const float*)d_in[0];
    const void*  ei = (const void*)d_in[1];
    const float* W  = (const float*)d_in[2];
    const float* b  = (const float*)d_in[3];
    float* out = (float*)d_out;

    const int n = NN, e = EE;
    const int T = 256;

    k_build<<<NB, 1024>>>(ei, n, e);

    int prop_blocks = (n * 32 + T - 1) / T;   // warp per row
    k_prop1      <<<prop_blocks, T>>>((const float4*)x, n);
    k_prop2_gemm <<<prop_blocks, T>>>(W, b, out, n);
}

// round 7
// speedup vs baseline: 1.0774x; 1.0646x over previous
#include <cuda_runtime.h>
#include <cuda_fp16.h>
#include <math.h>

// Problem constants (N,D,C,E,K = 100000,64,40,1600000,2)
#define NN 100000
#define DD 64
#define CC 40
#define EE 1600000
#define NBLK_SCAN 98             // 98*1024 >= NN
#define R4H 8                    // uint4 (8 halves) per fp16 row

// ---- device scratch (__device__ globals; allocation APIs are banned) ----
__device__ int    g_mode;        // 64 if edge_index is int64, else 32
__device__ int    g_deg[NN];     // edge count per row (excl self loop)
__device__ float  g_dis[NN];     // rsqrt(deg+1)
__device__ int    g_rowptr[NN + 1];
__device__ int    g_rank[EE];    // within-row rank of each edge
__device__ int    g_bsums[NBLK_SCAN];
__device__ int2   g_colw[EE];    // (col, half2(w,w) bits)
__device__ uint4  g_xh [(size_t)NN * R4H];   // x in fp16
__device__ uint4  g_xh1[(size_t)NN * R4H];   // hop-1 output in fp16

// ---------------------------------------------------------------------
// 0) init: deg=0, convert x -> fp16, detect edge dtype
//    grid covers NN*R4H = 800000 threads
// ---------------------------------------------------------------------
__global__ void k_init_conv(const float4* __restrict__ x4,
                            const long long* __restrict__ ei64) {
    int i = blockIdx.x * blockDim.x + threadIdx.x;
    if (i < NN) g_deg[i] = 0;
    if (i < NN * R4H) {
        float4 p = x4[(size_t)i * 2];
        float4 q = x4[(size_t)i * 2 + 1];
        __half2 h;
        uint4 st;
        h = __floats2half2_rn(p.x, p.y); st.x = *(unsigned*)&h;
        h = __floats2half2_rn(p.z, p.w); st.y = *(unsigned*)&h;
        h = __floats2half2_rn(q.x, q.y); st.z = *(unsigned*)&h;
        h = __floats2half2_rn(q.z, q.w); st.w = *(unsigned*)&h;
        g_xh[i] = st;
    }
    if (blockIdx.x == 0 && threadIdx.x < 32) {
        int bad = 0;
        for (int k = threadIdx.x; k < 256; k += 32) {
            long long v = ei64[k];
            if (v < 0 || v >= NN) bad = 1;
        }
        unsigned ball = __ballot_sync(0xFFFFFFFFu, bad);
        if (threadIdx.x == 0) g_mode = ball ? 32 : 64;
    }
}

// ---------------------------------------------------------------------
// 1) degree count; atomic return value = within-row rank (stored)
// ---------------------------------------------------------------------
__global__ void k_count(const void* __restrict__ ei, int e) {
    int i = blockIdx.x * blockDim.x + threadIdx.x;   // pair index
    int epairs = e / 2;
    if (i >= epairs) return;
    int r0, r1;
    if (g_mode == 64) {
        longlong2 v = ((const longlong2*)ei)[i];
        r0 = (int)v.x; r1 = (int)v.y;
    } else {
        int2 v = ((const int2*)ei)[i];
        r0 = v.x; r1 = v.y;
    }
    int k0 = atomicAdd(&g_deg[r0], 1);
    int k1 = atomicAdd(&g_deg[r1], 1);
    ((int2*)g_rank)[i] = make_int2(k0, k1);
}

// ---------------------------------------------------------------------
// 2) scan: per-block exclusive scan of deg, then apply block offsets
// ---------------------------------------------------------------------
__global__ void k_scan_block(int n) {
    __shared__ int sh[1024];
    int i = blockIdx.x * 1024 + threadIdx.x;
    int v = (i < n) ? g_deg[i] : 0;
    sh[threadIdx.x] = v;
    __syncthreads();
    #pragma unroll
    for (int off = 1; off < 1024; off <<= 1) {
        int t = (threadIdx.x >= off) ? sh[threadIdx.x - off] : 0;
        __syncthreads();
        sh[threadIdx.x] += t;
        __syncthreads();
    }
    int incl = sh[threadIdx.x];
    if (i < n) g_rowptr[i] = incl - v;          // exclusive within block
    if (threadIdx.x == 1023) g_bsums[blockIdx.x] = incl;
}

__global__ void k_scan_apply(int n, int e) {
    __shared__ int sh_off;
    if (threadIdx.x < 32) {
        int s = 0;
        for (int i = threadIdx.x; i < blockIdx.x; i += 32) s += g_bsums[i];
        #pragma unroll
        for (int o = 16; o; o >>= 1) s += __shfl_xor_sync(0xFFFFFFFFu, s, o);
        if (threadIdx.x == 0) sh_off = s;
    }
    __syncthreads();
    int i = blockIdx.x * 1024 + threadIdx.x;
    if (i < n) {
        g_rowptr[i] += sh_off;
        g_dis[i] = rsqrtf((float)(g_deg[i] + 1));
        if (i == n - 1) g_rowptr[n] = e;
    }
}

// ---------------------------------------------------------------------
// 3) fill packed CSR: colw[rowptr[r]+rank] = (col, half2(dis[col]) bits)
// ---------------------------------------------------------------------
__global__ void k_fill(const void* __restrict__ ei, int e) {
    int i = blockIdx.x * blockDim.x + threadIdx.x;   // pair index
    int epairs = e / 2;
    if (i >= epairs) return;
    int r0, c0, r1, c1;
    if (g_mode == 64) {
        longlong2 rv = ((const longlong2*)ei)[i];
        longlong2 cv = ((const longlong2*)ei)[epairs + i];
        r0 = (int)rv.x; r1 = (int)rv.y;
        c0 = (int)cv.x; c1 = (int)cv.y;
    } else {
        int2 rv = ((const int2*)ei)[i];
        int2 cv = ((const int2*)ei)[epairs + i];
        r0 = rv.x; r1 = rv.y;
        c0 = cv.x; c1 = cv.y;
    }
    int2 rk = ((int2*)g_rank)[i];
    unsigned hb0 = __half_as_ushort(__float2half_rn(g_dis[c0]));
    unsigned hb1 = __half_as_ushort(__float2half_rn(g_dis[c1]));
    g_colw[g_rowptr[r0] + rk.x] = make_int2(c0, (int)(hb0 | (hb0 << 16)));
    g_colw[g_rowptr[r1] + rk.y] = make_int2(c1, (int)(hb1 | (hb1 << 16)));
}

// ---------------------------------------------------------------------
// quarter-warp fp16 gather: 8 lanes cover a 128B row, 4 edges per LDG.128
// group. HFMA2 accumulation, flushed to fp32 every <=16 edges.
// On return: a[0..7] = sum_c w_c * src_row(c)[8*fidx .. 8*fidx+7],
// replicated across all 4 subgroups.
// ---------------------------------------------------------------------
__device__ __forceinline__ void
gather_row_h(const uint4* __restrict__ src, int beg, int end, int lane,
             float* a) {
    const int hl   = lane >> 3;        // subgroup 0..3
    const int fidx = lane & 7;         // uint4 index within row
    #pragma unroll
    for (int i = 0; i < 8; i++) a[i] = 0.f;
    const __half2 z = __float2half2_rn(0.f);

    for (int base = beg; base < end; base += 32) {
        int m = end - base; if (m > 32) m = 32;
        int2 cw = make_int2(0, 0);               // pad: w=0 gathers row 0 harmlessly
        if (lane < m) cw = g_colw[base + lane];
        int me4 = (m + 3) & ~3;
        int j = 0;
        while (j < me4) {
            __half2 h0 = z, h1 = z, h2 = z, h3 = z;
            int jend = j + 16; if (jend > me4) jend = me4;
            for (; j < jend; j += 4) {
                int s = j + hl;
                int      c  = __shfl_sync(0xFFFFFFFFu, cw.x, s);
                unsigned wb = (unsigned)__shfl_sync(0xFFFFFFFFu, cw.y, s);
                __half2 w = *(__half2*)&wb;
                uint4 v = src[(size_t)c * R4H + fidx];
                h0 = __hfma2(w, *(__half2*)&v.x, h0);
                h1 = __hfma2(w, *(__half2*)&v.y, h1);
                h2 = __hfma2(w, *(__half2*)&v.z, h2);
                h3 = __hfma2(w, *(__half2*)&v.w, h3);
            }
            float2 f;
            f = __half22float2(h0); a[0] += f.x; a[1] += f.y;
            f = __half22float2(h1); a[2] += f.x; a[3] += f.y;
            f = __half22float2(h2); a[4] += f.x; a[5] += f.y;
            f = __half22float2(h3); a[6] += f.x; a[7] += f.y;
        }
    }
    #pragma unroll
    for (int i = 0; i < 8; i++) {
        a[i] += __shfl_xor_sync(0xFFFFFFFFu, a[i], 8);
        a[i] += __shfl_xor_sync(0xFFFFFFFFu, a[i], 16);
    }
}

// ---------------------------------------------------------------------
// 4) hop 1: g_xh1[r] = fp16( dis[r]*gather(xh) + dis[r]^2*x[r] )
// ---------------------------------------------------------------------
__global__ void __launch_bounds__(256)
k_prop1(const float4* __restrict__ x4, int n) {
    int warp = (blockIdx.x * blockDim.x + threadIdx.x) >> 5;
    int lane = threadIdx.x & 31;
    if (warp >= n) return;

    float a[8];
    gather_row_h(g_xh, g_rowptr[warp], g_rowptr[warp + 1], lane, a);

    if (lane < 8) {
        float dr = g_dis[warp];
        float sl = dr * dr;
        float4 xa = x4[(size_t)warp * 16 + lane * 2];
        float4 xb = x4[(size_t)warp * 16 + lane * 2 + 1];
        float o0 = dr * a[0] + sl * xa.x;
        float o1 = dr * a[1] + sl * xa.y;
        float o2 = dr * a[2] + sl * xa.z;
        float o3 = dr * a[3] + sl * xa.w;
        float o4 = dr * a[4] + sl * xb.x;
        float o5 = dr * a[5] + sl * xb.y;
        float o6 = dr * a[6] + sl * xb.z;
        float o7 = dr * a[7] + sl * xb.w;
        __half2 h;
        uint4 st;
        h = __floats2half2_rn(o0, o1); st.x = *(unsigned*)&h;
        h = __floats2half2_rn(o2, o3); st.y = *(unsigned*)&h;
        h = __floats2half2_rn(o4, o5); st.z = *(unsigned*)&h;
        h = __floats2half2_rn(o6, o7); st.w = *(unsigned*)&h;
        g_xh1[(size_t)warp * R4H + lane] = st;
    }
}

// ---------------------------------------------------------------------
// 5) fused hop 2 + GEMM + log_softmax
// ---------------------------------------------------------------------
#define WT_STRIDE 68
__global__ void __launch_bounds__(256)
k_prop2_gemm(const float* __restrict__ W, const float* __restrict__ b,
             float* __restrict__ out, int n) {
    __shared__ float Wt[CC * WT_STRIDE];        // transposed W, pad 68
    __shared__ float bs[CC];
    __shared__ float4 hsm[8][16];               // per-warp h staging

    for (int i = threadIdx.x; i < DD * CC; i += blockDim.x) {
        int k = i / CC, c = i % CC;
        Wt[c * WT_STRIDE + k] = W[i];
    }
    for (int i = threadIdx.x; i < CC; i += blockDim.x) bs[i] = b[i];
    __syncthreads();

    int warp = (blockIdx.x * blockDim.x + threadIdx.x) >> 5;
    int wblk = threadIdx.x >> 5;
    int lane = threadIdx.x & 31;
    if (warp >= n) return;

    // ---- hop 2 ----
    float a[8];
    gather_row_h(g_xh1, g_rowptr[warp], g_rowptr[warp + 1], lane, a);

    if (lane < 8) {
        float dr = g_dis[warp];
        float sl = dr * dr;
        uint4 xs = g_xh1[(size_t)warp * R4H + lane];
        float2 f0 = __half22float2(*(__half2*)&xs.x);
        float2 f1 = __half22float2(*(__half2*)&xs.y);
        float2 f2 = __half22float2(*(__half2*)&xs.z);
        float2 f3 = __half22float2(*(__half2*)&xs.w);
        float4 ha, hb;
        ha.x = dr * a[0] + sl * f0.x;
        ha.y = dr * a[1] + sl * f0.y;
        ha.z = dr * a[2] + sl * f1.x;
        ha.w = dr * a[3] + sl * f1.y;
        hb.x = dr * a[4] + sl * f2.x;
        hb.y = dr * a[5] + sl * f2.y;
        hb.z = dr * a[6] + sl * f3.x;
        hb.w = dr * a[7] + sl * f3.y;
        hsm[wblk][lane * 2]     = ha;
        hsm[wblk][lane * 2 + 1] = hb;
    }
    __syncwarp();

    // ---- GEMM: lane owns cols {lane, lane+32 (lanes 0..7)} ----
    float acc0 = bs[lane];
    bool has2 = (lane < CC - 32);
    float acc1 = has2 ? bs[lane + 32] : 0.f;
    const float4* w0p = (const float4*)(Wt + lane * WT_STRIDE);
    const float4* w1p = (const float4*)(Wt + (lane + 32) * WT_STRIDE);
    #pragma unroll
    for (int k4 = 0; k4 < 16; k4++) {
        float4 hv = hsm[wblk][k4];              // broadcast LDS.128
        float4 w0 = w0p[k4];
        acc0 += hv.x * w0.x + hv.y * w0.y + hv.z * w0.z + hv.w * w0.w;
        if (has2) {
            float4 w1 = w1p[k4];
            acc1 += hv.x * w1.x + hv.y * w1.y + hv.z * w1.z + hv.w * w1.w;
        }
    }

    // ---- log_softmax over 40 logits ----
    float m = acc0;
    if (has2) m = fmaxf(m, acc1);
    #pragma unroll
    for (int off = 16; off; off >>= 1)
        m = fmaxf(m, __shfl_xor_sync(0xFFFFFFFFu, m, off));

    float s = __expf(acc0 - m);
    if (has2) s += __expf(acc1 - m);
    #pragma unroll
    for (int off = 16; off; off >>= 1)
        s += __shfl_xor_sync(0xFFFFFFFFu, s, off);

    float lse = m + __logf(s);
    out[(size_t)warp * CC + lane] = acc0 - lse;
    if (has2) out[(size_t)warp * CC + lane + 32] = acc1 - lse;
}

// ---------------------------------------------------------------------
extern "C" void kernel_launch(void* const* d_in, const int* in_sizes, int n_in,
                              void* d_out, int out_size) {
    const float* x  = (const float*)d_in[0];
    const void*  ei = (const void*)d_in[1];
    const float* W  = (const float*)d_in[2];
    const float* b  = (const float*)d_in[3];
    float* out = (float*)d_out;

    const int n = NN, e = EE;
    const int T = 256;
    const int epairs = e / 2;

    k_init_conv <<<(n * R4H + T - 1) / T, T>>>((const float4*)x, (const long long*)ei);
    k_count     <<<(epairs + T - 1) / T, T>>>(ei, e);
    k_scan_block<<<NBLK_SCAN, 1024>>>(n);
    k_scan_apply<<<NBLK_SCAN, 1024>>>(n, e);
    k_fill      <<<(epairs + T - 1) / T, T>>>(ei, e);

    int prop_blocks = (n * 32 + T - 1) / T;   // warp per row
    k_prop1     <<<prop_blocks, T>>>((const float4*)x, n);
    k_prop2_gemm<<<prop_blocks, T>>>(W, b, out, n);
}

// round 8
// speedup vs baseline: 1.4259x; 1.3234x over previous
#include <cuda_runtime.h>
#include <cuda_fp16.h>
#include <math.h>

// Problem constants (N,D,C,E,K = 100000,64,40,1600000,2)
#define NN 100000
#define DD 64
#define CC 40
#define EE 1600000
#define NBLK_SCAN 98             // 98*1024 >= NN
#define R4H 8                    // uint4 (8 halves) per fp16 row

// ---- device scratch (__device__ globals; allocation APIs are banned) ----
__device__ int    g_mode;        // 64 if edge_index is int64, else 32
__device__ int    g_deg[NN];     // edge count per row (excl self loop)
__device__ float  g_dis[NN];     // rsqrt(deg+1)
__device__ int    g_rowptr[NN + 1];
__device__ int    g_rank[EE];    // within-row rank of each edge
__device__ int    g_bsums[NBLK_SCAN];
__device__ int2   g_colw[EE];    // (col, half2(w,w) bits)
__device__ uint4  g_xh [(size_t)NN * R4H];   // x fp16; later reused as h (hop-2 out)
__device__ uint4  g_xh1[(size_t)NN * R4H];   // hop-1 output fp16

// ---------------------------------------------------------------------
// 0) init: deg=0, convert x -> fp16, detect edge dtype
// ---------------------------------------------------------------------
__global__ void k_init_conv(const float4* __restrict__ x4,
                            const long long* __restrict__ ei64) {
    int i = blockIdx.x * blockDim.x + threadIdx.x;
    if (i < NN) g_deg[i] = 0;
    if (i < NN * R4H) {
        float4 p = x4[(size_t)i * 2];
        float4 q = x4[(size_t)i * 2 + 1];
        __half2 h;
        uint4 st;
        h = __floats2half2_rn(p.x, p.y); st.x = *(unsigned*)&h;
        h = __floats2half2_rn(p.z, p.w); st.y = *(unsigned*)&h;
        h = __floats2half2_rn(q.x, q.y); st.z = *(unsigned*)&h;
        h = __floats2half2_rn(q.z, q.w); st.w = *(unsigned*)&h;
        g_xh[i] = st;
    }
    if (blockIdx.x == 0 && threadIdx.x < 32) {
        int bad = 0;
        for (int k = threadIdx.x; k < 256; k += 32) {
            long long v = ei64[k];
            if (v < 0 || v >= NN) bad = 1;
        }
        unsigned ball = __ballot_sync(0xFFFFFFFFu, bad);
        if (threadIdx.x == 0) g_mode = ball ? 32 : 64;
    }
}

// ---------------------------------------------------------------------
// 1) degree count; atomic return value = within-row rank (stored)
// ---------------------------------------------------------------------
__global__ void k_count(const void* __restrict__ ei, int e) {
    int i = blockIdx.x * blockDim.x + threadIdx.x;   // pair index
    int epairs = e / 2;
    if (i >= epairs) return;
    int r0, r1;
    if (g_mode == 64) {
        longlong2 v = ((const longlong2*)ei)[i];
        r0 = (int)v.x; r1 = (int)v.y;
    } else {
        int2 v = ((const int2*)ei)[i];
        r0 = v.x; r1 = v.y;
    }
    int k0 = atomicAdd(&g_deg[r0], 1);
    int k1 = atomicAdd(&g_deg[r1], 1);
    ((int2*)g_rank)[i] = make_int2(k0, k1);
}

// ---------------------------------------------------------------------
// 2) scan: per-block exclusive scan of deg, then apply block offsets
// ---------------------------------------------------------------------
__global__ void k_scan_block(int n) {
    __shared__ int sh[1024];
    int i = blockIdx.x * 1024 + threadIdx.x;
    int v = (i < n) ? g_deg[i] : 0;
    sh[threadIdx.x] = v;
    __syncthreads();
    #pragma unroll
    for (int off = 1; off < 1024; off <<= 1) {
        int t = (threadIdx.x >= off) ? sh[threadIdx.x - off] : 0;
        __syncthreads();
        sh[threadIdx.x] += t;
        __syncthreads();
    }
    int incl = sh[threadIdx.x];
    if (i < n) g_rowptr[i] = incl - v;
    if (threadIdx.x == 1023) g_bsums[blockIdx.x] = incl;
}

__global__ void k_scan_apply(int n, int e) {
    __shared__ int sh_off;
    if (threadIdx.x < 32) {
        int s = 0;
        for (int i = threadIdx.x; i < blockIdx.x; i += 32) s += g_bsums[i];
        #pragma unroll
        for (int o = 16; o; o >>= 1) s += __shfl_xor_sync(0xFFFFFFFFu, s, o);
        if (threadIdx.x == 0) sh_off = s;
    }
    __syncthreads();
    int i = blockIdx.x * 1024 + threadIdx.x;
    if (i < n) {
        g_rowptr[i] += sh_off;
        g_dis[i] = rsqrtf((float)(g_deg[i] + 1));
        if (i == n - 1) g_rowptr[n] = e;
    }
}

// ---------------------------------------------------------------------
// 3) fill packed CSR: colw[rowptr[r]+rank] = (col, half2(dis[col]) bits)
// ---------------------------------------------------------------------
__global__ void k_fill(const void* __restrict__ ei, int e) {
    int i = blockIdx.x * blockDim.x + threadIdx.x;   // pair index
    int epairs = e / 2;
    if (i >= epairs) return;
    int r0, c0, r1, c1;
    if (g_mode == 64) {
        longlong2 rv = ((const longlong2*)ei)[i];
        longlong2 cv = ((const longlong2*)ei)[epairs + i];
        r0 = (int)rv.x; r1 = (int)rv.y;
        c0 = (int)cv.x; c1 = (int)cv.y;
    } else {
        int2 rv = ((const int2*)ei)[i];
        int2 cv = ((const int2*)ei)[epairs + i];
        r0 = rv.x; r1 = rv.y;
        c0 = cv.x; c1 = cv.y;
    }
    int2 rk = ((int2*)g_rank)[i];
    unsigned hb0 = __half_as_ushort(__float2half_rn(g_dis[c0]));
    unsigned hb1 = __half_as_ushort(__float2half_rn(g_dis[c1]));
    g_colw[g_rowptr[r0] + rk.x] = make_int2(c0, (int)(hb0 | (hb0 << 16)));
    g_colw[g_rowptr[r1] + rk.y] = make_int2(c1, (int)(hb1 | (hb1 << 16)));
}

// ---------------------------------------------------------------------
// quarter-warp fp16 gather (8 lanes per 128B row, 4 edges in flight)
// ---------------------------------------------------------------------
__device__ __forceinline__ void
gather_row_h(const uint4* __restrict__ src, int beg, int end, int lane,
             float* a) {
    const int hl   = lane >> 3;
    const int fidx = lane & 7;
    #pragma unroll
    for (int i = 0; i < 8; i++) a[i] = 0.f;
    const __half2 z = __float2half2_rn(0.f);

    for (int base = beg; base < end; base += 32) {
        int m = end - base; if (m > 32) m = 32;
        int2 cw = make_int2(0, 0);
        if (lane < m) cw = g_colw[base + lane];
        int me4 = (m + 3) & ~3;
        int j = 0;
        while (j < me4) {
            __half2 h0 = z, h1 = z, h2 = z, h3 = z;
            int jend = j + 16; if (jend > me4) jend = me4;
            for (; j < jend; j += 4) {
                int s = j + hl;
                int      c  = __shfl_sync(0xFFFFFFFFu, cw.x, s);
                unsigned wb = (unsigned)__shfl_sync(0xFFFFFFFFu, cw.y, s);
                __half2 w = *(__half2*)&wb;
                uint4 v = src[(size_t)c * R4H + fidx];
                h0 = __hfma2(w, *(__half2*)&v.x, h0);
                h1 = __hfma2(w, *(__half2*)&v.y, h1);
                h2 = __hfma2(w, *(__half2*)&v.z, h2);
                h3 = __hfma2(w, *(__half2*)&v.w, h3);
            }
            float2 f;
            f = __half22float2(h0); a[0] += f.x; a[1] += f.y;
            f = __half22float2(h1); a[2] += f.x; a[3] += f.y;
            f = __half22float2(h2); a[4] += f.x; a[5] += f.y;
            f = __half22float2(h3); a[6] += f.x; a[7] += f.y;
        }
    }
    #pragma unroll
    for (int i = 0; i < 8; i++) {
        a[i] += __shfl_xor_sync(0xFFFFFFFFu, a[i], 8);
        a[i] += __shfl_xor_sync(0xFFFFFFFFu, a[i], 16);
    }
}

// ---------------------------------------------------------------------
// 4) hop 1: g_xh1[r] = fp16( dis[r]*gather(g_xh) + dis[r]^2*x[r] )
// ---------------------------------------------------------------------
__global__ void __launch_bounds__(256)
k_prop1(const float4* __restrict__ x4, int n) {
    int warp = (blockIdx.x * blockDim.x + threadIdx.x) >> 5;
    int lane = threadIdx.x & 31;
    if (warp >= n) return;

    float a[8];
    gather_row_h(g_xh, g_rowptr[warp], g_rowptr[warp + 1], lane, a);

    if (lane < 8) {
        float dr = g_dis[warp];
        float sl = dr * dr;
        float4 xa = x4[(size_t)warp * 16 + lane * 2];
        float4 xb = x4[(size_t)warp * 16 + lane * 2 + 1];
        float o0 = dr * a[0] + sl * xa.x;
        float o1 = dr * a[1] + sl * xa.y;
        float o2 = dr * a[2] + sl * xa.z;
        float o3 = dr * a[3] + sl * xa.w;
        float o4 = dr * a[4] + sl * xb.x;
        float o5 = dr * a[5] + sl * xb.y;
        float o6 = dr * a[6] + sl * xb.z;
        float o7 = dr * a[7] + sl * xb.w;
        __half2 h;
        uint4 st;
        h = __floats2half2_rn(o0, o1); st.x = *(unsigned*)&h;
        h = __floats2half2_rn(o2, o3); st.y = *(unsigned*)&h;
        h = __floats2half2_rn(o4, o5); st.z = *(unsigned*)&h;
        h = __floats2half2_rn(o6, o7); st.w = *(unsigned*)&h;
        g_xh1[(size_t)warp * R4H + lane] = st;
    }
}

// ---------------------------------------------------------------------
// 5) hop 2: g_xh[r] (reused) = fp16( dis[r]*gather(g_xh1) + dis[r]^2*xh1[r] )
// ---------------------------------------------------------------------
__global__ void __launch_bounds__(256)
k_prop2(int n) {
    int warp = (blockIdx.x * blockDim.x + threadIdx.x) >> 5;
    int lane = threadIdx.x & 31;
    if (warp >= n) return;

    float a[8];
    gather_row_h(g_xh1, g_rowptr[warp], g_rowptr[warp + 1], lane, a);

    if (lane < 8) {
        float dr = g_dis[warp];
        float sl = dr * dr;
        uint4 xs = g_xh1[(size_t)warp * R4H + lane];
        float2 f0 = __half22float2(*(__half2*)&xs.x);
        float2 f1 = __half22float2(*(__half2*)&xs.y);
        float2 f2 = __half22float2(*(__half2*)&xs.z);
        float2 f3 = __half22float2(*(__half2*)&xs.w);
        float o0 = dr * a[0] + sl * f0.x;
        float o1 = dr * a[1] + sl * f0.y;
        float o2 = dr * a[2] + sl * f1.x;
        float o3 = dr * a[3] + sl * f1.y;
        float o4 = dr * a[4] + sl * f2.x;
        float o5 = dr * a[5] + sl * f2.y;
        float o6 = dr * a[6] + sl * f3.x;
        float o7 = dr * a[7] + sl * f3.y;
        __half2 h;
        uint4 st;
        h = __floats2half2_rn(o0, o1); st.x = *(unsigned*)&h;
        h = __floats2half2_rn(o2, o3); st.y = *(unsigned*)&h;
        h = __floats2half2_rn(o4, o5); st.z = *(unsigned*)&h;
        h = __floats2half2_rn(o6, o7); st.w = *(unsigned*)&h;
        g_xh[(size_t)warp * R4H + lane] = st;   // reuse g_xh as h buffer
    }
}

// ---------------------------------------------------------------------
// 6) GEMM + log_softmax via mma.sync.m16n8k16 (f16 x f16 -> f32)
//    block = 128 rows (8 warps x 16 rows); out = log_softmax(h @ W + b)
// ---------------------------------------------------------------------
#define HS_STRIDE 9              // uint4 per smem h row (144B, conflict-free ldmatrix)
#define WS_STRIDE 42             // fp32 W smem row stride
__global__ void __launch_bounds__(256)
k_gemm_lsm(const float* __restrict__ W, const float* __restrict__ b,
           float* __restrict__ out, int n) {
    __shared__ uint4 hs[128 * HS_STRIDE];       // 18KB fp16 h tile
    __shared__ float Ws[DD * WS_STRIDE];        // 10.5KB
    __shared__ float bs[CC];

    const int tid  = threadIdx.x;
    const int warp = tid >> 5;
    const int lane = tid & 31;
    const int row0 = blockIdx.x * 128;

    // stage W (fp32) + bias
    for (int i = tid; i < DD * CC; i += 256) {
        int k = i / CC, c = i % CC;
        Ws[k * WS_STRIDE + c] = W[i];
    }
    if (tid < CC) bs[tid] = b[tid];

    // stage h tile: 128 rows x 8 uint4, zero-pad beyond n
    #pragma unroll
    for (int it = 0; it < 4; it++) {
        int idx = tid + it * 256;               // 0..1023
        int r = idx >> 3, q = idx & 7;
        int grow = row0 + r;
        uint4 v = make_uint4(0u, 0u, 0u, 0u);
        if (grow < n) v = g_xh[(size_t)grow * R4H + q];
        hs[r * HS_STRIDE + q] = v;
    }
    __syncthreads();

    // ---- A fragments: 4 ktiles via ldmatrix.x4 ----
    unsigned hs_base = (unsigned)__cvta_generic_to_shared(hs);
    unsigned A[4][4];
    {
        int r_in = lane & 15;
        int half16 = (lane >> 4) * 16;          // 0 or 16 bytes (k 0-7 vs 8-15)
        unsigned rowaddr = hs_base + (unsigned)((warp * 16 + r_in) * (HS_STRIDE * 16)) + half16;
        #pragma unroll
        for (int kt = 0; kt < 4; kt++) {
            unsigned addr = rowaddr + kt * 32;
            asm volatile("ldmatrix.sync.aligned.m8n8.x4.shared.b16 {%0,%1,%2,%3}, [%4];"
                         : "=r"(A[kt][0]), "=r"(A[kt][1]), "=r"(A[kt][2]), "=r"(A[kt][3])
                         : "r"(addr));
        }
    }

    // ---- 5 n-tiles of mma, accumulate into C[5][4] ----
    const int t = lane & 3, g = lane >> 2;
    float C[5][4];
    #pragma unroll
    for (int nt = 0; nt < 5; nt++) {
        int col0 = nt * 8 + 2 * t;
        float bi0 = bs[col0], bi1 = bs[col0 + 1];
        C[nt][0] = bi0; C[nt][1] = bi1; C[nt][2] = bi0; C[nt][3] = bi1;
        int nn = nt * 8 + g;
        #pragma unroll
        for (int kt = 0; kt < 4; kt++) {
            int k0 = kt * 16 + 2 * t;
            __half2 hb0 = __floats2half2_rn(Ws[k0 * WS_STRIDE + nn],
                                            Ws[(k0 + 1) * WS_STRIDE + nn]);
            __half2 hb1 = __floats2half2_rn(Ws[(k0 + 8) * WS_STRIDE + nn],
                                            Ws[(k0 + 9) * WS_STRIDE + nn]);
            unsigned B0 = *(unsigned*)&hb0;
            unsigned B1 = *(unsigned*)&hb1;
            asm volatile(
                "mma.sync.aligned.m16n8k16.row.col.f32.f16.f16.f32 "
                "{%0,%1,%2,%3}, {%4,%5,%6,%7}, {%8,%9}, {%0,%1,%2,%3};"
                : "+f"(C[nt][0]), "+f"(C[nt][1]), "+f"(C[nt][2]), "+f"(C[nt][3])
                : "r"(A[kt][0]), "r"(A[kt][1]), "r"(A[kt][2]), "r"(A[kt][3]),
                  "r"(B0), "r"(B1));
        }
    }

    // ---- log_softmax per row (rows g and g+8 of warp tile) ----
    float m0 = -1e30f, m1 = -1e30f;
    #pragma unroll
    for (int nt = 0; nt < 5; nt++) {
        m0 = fmaxf(m0, fmaxf(C[nt][0], C[nt][1]));
        m1 = fmaxf(m1, fmaxf(C[nt][2], C[nt][3]));
    }
    m0 = fmaxf(m0, __shfl_xor_sync(0xFFFFFFFFu, m0, 1));
    m0 = fmaxf(m0, __shfl_xor_sync(0xFFFFFFFFu, m0, 2));
    m1 = fmaxf(m1, __shfl_xor_sync(0xFFFFFFFFu, m1, 1));
    m1 = fmaxf(m1, __shfl_xor_sync(0xFFFFFFFFu, m1, 2));

    float s0 = 0.f, s1 = 0.f;
    #pragma unroll
    for (int nt = 0; nt < 5; nt++) {
        s0 += __expf(C[nt][0] - m0) + __expf(C[nt][1] - m0);
        s1 += __expf(C[nt][2] - m1) + __expf(C[nt][3] - m1);
    }
    s0 += __shfl_xor_sync(0xFFFFFFFFu, s0, 1);
    s0 += __shfl_xor_sync(0xFFFFFFFFu, s0, 2);
    s1 += __shfl_xor_sync(0xFFFFFFFFu, s1, 1);
    s1 += __shfl_xor_sync(0xFFFFFFFFu, s1, 2);

    float lse0 = m0 + __logf(s0);
    float lse1 = m1 + __logf(s1);

    int grow0 = row0 + warp * 16 + g;
    int grow1 = grow0 + 8;
    #pragma unroll
    for (int nt = 0; nt < 5; nt++) {
        int col0 = nt * 8 + 2 * t;
        if (grow0 < n)
            *(float2*)(out + (size_t)grow0 * CC + col0) =
                make_float2(C[nt][0] - lse0, C[nt][1] - lse0);
        if (grow1 < n)
            *(float2*)(out + (size_t)grow1 * CC + col0) =
                make_float2(C[nt][2] - lse1, C[nt][3] - lse1);
    }
}

// ---------------------------------------------------------------------
extern "C" void kernel_launch(void* const* d_in, const int* in_sizes, int n_in,
                              void* d_out, int out_size) {
    const float* x  = (const float*)d_in[0];
    const void*  ei = (const void*)d_in[1];
    const float* W  = (const float*)d_in[2];
    const float* b  = (const float*)d_in[3];
    float* out = (float*)d_out;

    const int n = NN, e = EE;
    const int T = 256;
    const int epairs = e / 2;

    k_init_conv <<<(n * R4H + T - 1) / T, T>>>((const float4*)x, (const long long*)ei);
    k_count     <<<(epairs + T - 1) / T, T>>>(ei, e);
    k_scan_block<<<NBLK_SCAN, 1024>>>(n);
    k_scan_apply<<<NBLK_SCAN, 1024>>>(n, e);
    k_fill      <<<(epairs + T - 1) / T, T>>>(ei, e);

    int prop_blocks = (n * 32 + T - 1) / T;   // warp per row
    k_prop1     <<<prop_blocks, T>>>((const float4*)x, n);
    k_prop2     <<<prop_blocks, T>>>(n);
    k_gemm_lsm  <<<(n + 127) / 128, T>>>(W, b, out, n);
}